// round 2
// baseline (speedup 1.0000x reference)
#include <cuda_runtime.h>
#include <cuda_bf16.h>
#include <cstdint>
#include <cstddef>

// ===================== problem dims =====================
static constexpr int BATCH = 16384;
static constexpr int IN_F  = 2048;
static constexpr int OUT_F = 2048;
static constexpr int KK2   = 2 * IN_F;   // scratch K layout per row: [hi | lo]

// Effective GEMM: C = A_hi*W_hi + A_lo*W_hi + A_hi*W_lo  (bf16 inputs, fp32 accum)

// ===================== device scratch (no allocations allowed) =====================
__device__ __nv_bfloat16 g_A[(size_t)BATCH * KK2];  // 128 MiB
__device__ __nv_bfloat16 g_W[(size_t)OUT_F * KK2];  //  16 MiB

// ===================== helpers =====================
__device__ __forceinline__ uint32_t smem_u32(const void* p) {
    uint32_t a;
    asm("{ .reg .u64 t; cvta.to.shared.u64 t, %1; cvt.u32.u64 %0, t; }" : "=r"(a) : "l"(p));
    return a;
}
__device__ __forceinline__ void cp16(uint32_t smem_dst, const void* gmem_src) {
    asm volatile("cp.async.cg.shared.global [%0], [%1], 16;" :: "r"(smem_dst), "l"(gmem_src));
}
#define CP_COMMIT() asm volatile("cp.async.commit_group;" ::: "memory")
#define CP_WAIT2()  asm volatile("cp.async.wait_group 2;" ::: "memory")

__device__ __forceinline__ void ldsm_x4(uint32_t (&r)[4], uint32_t addr) {
    asm volatile("ldmatrix.sync.aligned.m8n8.x4.shared.b16 {%0,%1,%2,%3}, [%4];"
                 : "=r"(r[0]), "=r"(r[1]), "=r"(r[2]), "=r"(r[3]) : "r"(addr));
}
__device__ __forceinline__ void mma16816(float (&d)[4], const uint32_t (&a)[4],
                                         uint32_t b0, uint32_t b1) {
    asm volatile(
        "mma.sync.aligned.m16n8k16.row.col.f32.bf16.bf16.f32 "
        "{%0,%1,%2,%3}, {%4,%5,%6,%7}, {%8,%9}, {%0,%1,%2,%3};"
        : "+f"(d[0]), "+f"(d[1]), "+f"(d[2]), "+f"(d[3])
        : "r"(a[0]), "r"(a[1]), "r"(a[2]), "r"(a[3]), "r"(b0), "r"(b1));
}

// SW128 swizzle (Swizzle<3,4,3>) — tile bases must be 1024B aligned
#define SWZ(o) ((o) ^ (((o) >> 3) & 0x70))

// ===================== conversion kernels =====================
__global__ void convert_x_kernel(const float* __restrict__ x, const float* __restrict__ alpha) {
    size_t i = (size_t)blockIdx.x * 256 + threadIdx.x;     // float4 index
    float a = alpha[0];
    bool fast = (a == 0.5f);
    float4 v = reinterpret_cast<const float4*>(x)[i];
    size_t e = i << 2;
    size_t row = e >> 11;          // / IN_F
    size_t col = e & (IN_F - 1);
    float s[4] = {v.x, v.y, v.z, v.w};
    union { __nv_bfloat16 h[4]; uint2 u; } H, L;
#pragma unroll
    for (int k = 0; k < 4; k++) {
        float t  = s[k];
        float at = fabsf(t);
        float p  = fast ? sqrtf(at) : powf(at, a);
        float sc = copysignf(p, t);
        H.h[k] = __float2bfloat16(sc);
        L.h[k] = __float2bfloat16(sc - __bfloat162float(H.h[k]));
    }
    __nv_bfloat16* base = g_A + row * KK2 + col;
    *reinterpret_cast<uint2*>(base)        = H.u;
    *reinterpret_cast<uint2*>(base + IN_F) = L.u;
}

__global__ void convert_w_kernel(const int* __restrict__ wq, const float* __restrict__ cent) {
    __shared__ float c[16];
    if (threadIdx.x < 16) c[threadIdx.x] = cent[threadIdx.x];
    __syncthreads();
    size_t i = (size_t)blockIdx.x * 256 + threadIdx.x;     // int4 index
    int4 q = reinterpret_cast<const int4*>(wq)[i];
    size_t e = i << 2;
    size_t row = e >> 11;
    size_t col = e & (IN_F - 1);
    float w[4] = {c[q.x & 15], c[q.y & 15], c[q.z & 15], c[q.w & 15]};
    union { __nv_bfloat16 h[4]; uint2 u; } H, L;
#pragma unroll
    for (int k = 0; k < 4; k++) {
        H.h[k] = __float2bfloat16(w[k]);
        L.h[k] = __float2bfloat16(w[k] - __bfloat162float(H.h[k]));
    }
    __nv_bfloat16* base = g_W + row * KK2 + col;
    *reinterpret_cast<uint2*>(base)        = H.u;
    *reinterpret_cast<uint2*>(base + IN_F) = L.u;
}

// ===================== GEMM kernel (mma.sync, 4-stage cp.async) =====================
static constexpr int BM = 128;
static constexpr int BN = 256;
static constexpr int KC = 64;                     // K elems per stage (128B rows)
static constexpr int STAGES = 4;
static constexpr int A_BYTES = BM * KC * 2;       // 16 KiB
static constexpr int B_BYTES = BN * KC * 2;       // 32 KiB
static constexpr int STG = A_BYTES + B_BYTES;     // 48 KiB
static constexpr int SMEM_TOTAL = STAGES * STG + 1024;   // +1024 for alignment pad
static constexpr int NKC = 3 * IN_F / KC;         // 96 K-chunks (3 split terms)

__global__ void __launch_bounds__(256, 1)
gemm_kernel(float* __restrict__ out, const float* __restrict__ alpha) {
    extern __shared__ char smem_raw[];
    uint32_t sb = (smem_u32(smem_raw) + 1023u) & ~1023u;

    const int tid = threadIdx.x;
    const int wid = tid >> 5, lane = tid & 31;
    const int warp_m = wid & 1, warp_n = wid >> 1;        // 2 x 4 warps, 64x64 warp tile
    const int mb = blockIdx.x >> 3, nb = blockIdx.x & 7;  // n-minor for L2 A reuse
    const int m0 = mb * BM, n0 = nb * BN;

    // ---- per-thread cp.async source/dest mapping ----
    // A: 1024 chunks of 16B (128 rows x 8), B: 2048 chunks (256 rows x 8)
    const __nv_bfloat16* gA = g_A + (size_t)m0 * KK2;
    const __nv_bfloat16* gW = g_W + (size_t)n0 * KK2;

    // ---- ldmatrix per-lane address components ----
    const int a_row  = warp_m * 64 + (lane & 15);
    const int a_ext  = (lane >> 4) * 16;                  // k-halves
    const int b_row  = warp_n * 64 + (lane & 7) + ((lane >> 4) << 3);
    const int b_ext  = ((lane >> 3) & 1) * 16;

    float acc[4][8][4];
#pragma unroll
    for (int im = 0; im < 4; im++)
#pragma unroll
        for (int in = 0; in < 8; in++)
#pragma unroll
            for (int r = 0; r < 4; r++) acc[im][in][r] = 0.0f;

    // K-chunk -> (acol, bcol) in scratch: term0 hi/hi, term1 lo/hi, term2 hi/lo
    auto cols_of = [](int kc, int& acol, int& bcol) {
        int term = kc >> 5, inner = kc & 31;
        acol = ((term == 1) ? IN_F : 0) + inner * KC;
        bcol = ((term == 2) ? IN_F : 0) + inner * KC;
    };

    auto load_stage = [&](int slot, int kc) {
        int acol, bcol;
        cols_of(kc, acol, bcol);
        uint32_t sA = sb + slot * STG;
        uint32_t sB = sA + A_BYTES;
#pragma unroll
        for (int i = 0; i < 4; i++) {                      // A: 4 chunks/thread
            int c = tid + i * 256;
            int row = c >> 3, col = c & 7;
            cp16(sA + SWZ(row * 128 + col * 16), gA + (size_t)row * KK2 + acol + col * 8);
        }
#pragma unroll
        for (int i = 0; i < 8; i++) {                      // B: 8 chunks/thread
            int c = tid + i * 256;
            int row = c >> 3, col = c & 7;
            cp16(sB + SWZ(row * 128 + col * 16), gW + (size_t)row * KK2 + bcol + col * 8);
        }
    };

    // ---- prologue: stages 0..STAGES-2 ----
#pragma unroll
    for (int s = 0; s < STAGES - 1; s++) { load_stage(s, s); CP_COMMIT(); }

    // ---- main loop ----
    for (int kc = 0; kc < NKC; kc++) {
        CP_WAIT2();            // group kc complete (in-order groups)
        __syncthreads();       // data visible; all warps done reading slot being overwritten

        int nkc = kc + STAGES - 1;
        if (nkc < NKC) load_stage(nkc & (STAGES - 1), nkc);
        CP_COMMIT();           // always one group per iter (may be empty)

        uint32_t sA = sb + (kc & (STAGES - 1)) * STG;
        uint32_t sB = sA + A_BYTES;

#pragma unroll
        for (int ks = 0; ks < 4; ks++) {
            uint32_t af[4][4], bf[4][4];
#pragma unroll
            for (int im = 0; im < 4; im++)
                ldsm_x4(af[im], sA + SWZ((a_row + im * 16) * 128 + ks * 32 + a_ext));
#pragma unroll
            for (int jn = 0; jn < 4; jn++)
                ldsm_x4(bf[jn], sB + SWZ((b_row + jn * 16) * 128 + ks * 32 + b_ext));
#pragma unroll
            for (int im = 0; im < 4; im++)
#pragma unroll
                for (int jn = 0; jn < 4; jn++) {
                    mma16816(acc[im][2 * jn + 0], af[im], bf[jn][0], bf[jn][1]);
                    mma16816(acc[im][2 * jn + 1], af[im], bf[jn][2], bf[jn][3]);
                }
        }
    }

    // ---- epilogue: y = sign(d) * |d|^(1/a) ----
    float a = alpha[0];
    bool fast = (a == 0.5f);
    float inv = 1.0f / a;
    const int er = m0 + warp_m * 64 + (lane >> 2);
    const int ec = n0 + warp_n * 64 + (lane & 3) * 2;
#pragma unroll
    for (int im = 0; im < 4; im++) {
#pragma unroll
        for (int in = 0; in < 8; in++) {
            float d0 = acc[im][in][0], d1 = acc[im][in][1];
            float d2 = acc[im][in][2], d3 = acc[im][in][3];
            float2 v01, v23;
            if (fast) {
                v01.x = d0 * fabsf(d0); v01.y = d1 * fabsf(d1);
                v23.x = d2 * fabsf(d2); v23.y = d3 * fabsf(d3);
            } else {
                v01.x = copysignf(powf(fabsf(d0), inv), d0);
                v01.y = copysignf(powf(fabsf(d1), inv), d1);
                v23.x = copysignf(powf(fabsf(d2), inv), d2);
                v23.y = copysignf(powf(fabsf(d3), inv), d3);
            }
            int row = er + im * 16;
            int col = ec + in * 8;
            *reinterpret_cast<float2*>(out + (size_t)row * OUT_F + col) = v01;
            *reinterpret_cast<float2*>(out + (size_t)(row + 8) * OUT_F + col) = v23;
        }
    }
}

// ===================== launch =====================
extern "C" void kernel_launch(void* const* d_in, const int* in_sizes, int n_in,
                              void* d_out, int out_size) {
    const float* x = nullptr;
    const float* cent = nullptr;
    const float* alpha = nullptr;
    const int*   wq = nullptr;
    for (int i = 0; i < n_in; i++) {
        long s = in_sizes[i];
        if      (s == (long)BATCH * IN_F) x     = (const float*)d_in[i];
        else if (s == 16)                 cent  = (const float*)d_in[i];
        else if (s == 1)                  alpha = (const float*)d_in[i];
        else if (s == (long)OUT_F * IN_F) wq    = (const int*)d_in[i];
    }

    cudaFuncSetAttribute(gemm_kernel, cudaFuncAttributeMaxDynamicSharedMemorySize, SMEM_TOTAL);

    convert_x_kernel<<<(BATCH * IN_F / 4) / 256, 256>>>(x, alpha);
    convert_w_kernel<<<(OUT_F * IN_F / 4) / 256, 256>>>(wq, cent);
    gemm_kernel<<<(BATCH / BM) * (OUT_F / BN), 256, SMEM_TOTAL>>>((float*)d_out, alpha);
}

// round 3
// speedup vs baseline: 1.0195x; 1.0195x over previous
#include <cuda_runtime.h>
#include <cuda_bf16.h>
#include <cstdint>
#include <cstddef>

// ===================== problem dims =====================
static constexpr int BATCH = 16384;
static constexpr int IN_F  = 2048;
static constexpr int OUT_F = 2048;
static constexpr int KK2   = 2 * IN_F;   // scratch K layout per row: [hi | lo]

// Effective GEMM: C = A_hi*W_hi + A_lo*W_hi + A_hi*W_lo  (bf16 inputs, fp32 accum)

// ===================== device scratch (no allocations allowed) =====================
__device__ __nv_bfloat16 g_A[(size_t)BATCH * KK2];  // 128 MiB
__device__ __nv_bfloat16 g_W[(size_t)OUT_F * KK2];  //  16 MiB

// ===================== helpers =====================
__device__ __forceinline__ uint32_t smem_u32(const void* p) {
    uint32_t a;
    asm("{ .reg .u64 t; cvta.to.shared.u64 t, %1; cvt.u32.u64 %0, t; }" : "=r"(a) : "l"(p));
    return a;
}
__device__ __forceinline__ void cp16(uint32_t smem_dst, const void* gmem_src) {
    asm volatile("cp.async.cg.shared.global [%0], [%1], 16;" :: "r"(smem_dst), "l"(gmem_src));
}
#define CP_COMMIT() asm volatile("cp.async.commit_group;" ::: "memory")
#define CP_WAIT2()  asm volatile("cp.async.wait_group 2;" ::: "memory")

__device__ __forceinline__ void ldsm_x4(uint32_t (&r)[4], uint32_t addr) {
    asm volatile("ldmatrix.sync.aligned.m8n8.x4.shared.b16 {%0,%1,%2,%3}, [%4];"
                 : "=r"(r[0]), "=r"(r[1]), "=r"(r[2]), "=r"(r[3]) : "r"(addr));
}
__device__ __forceinline__ void mma16816(float (&d)[4], const uint32_t (&a)[4],
                                         uint32_t b0, uint32_t b1) {
    asm volatile(
        "mma.sync.aligned.m16n8k16.row.col.f32.bf16.bf16.f32 "
        "{%0,%1,%2,%3}, {%4,%5,%6,%7}, {%8,%9}, {%0,%1,%2,%3};"
        : "+f"(d[0]), "+f"(d[1]), "+f"(d[2]), "+f"(d[3])
        : "r"(a[0]), "r"(a[1]), "r"(a[2]), "r"(a[3]), "r"(b0), "r"(b1));
}

// SW128 swizzle (Swizzle<3,4,3>) — tile bases must be 1024B aligned
#define SWZ(o) ((o) ^ (((o) >> 3) & 0x70))

// ===================== merged conversion kernel =====================
// blocks [0, XB): x -> signed |x|^alpha -> bf16 hi/lo into g_A
// blocks [XB, XB+WB): W_q -> centroid gather -> bf16 hi/lo into g_W
static constexpr int XB = (BATCH * IN_F / 4) / 256;   // 32768 blocks
static constexpr int WB = (OUT_F * IN_F / 4) / 256;   //  4096 blocks

__global__ void convert_kernel(const float* __restrict__ x,
                               const int* __restrict__ wq,
                               const float* __restrict__ cent,
                               const float* __restrict__ alpha) {
    int bid = blockIdx.x;
    if (bid < XB) {
        size_t i = (size_t)bid * 256 + threadIdx.x;        // float4 index
        float a = alpha[0];
        bool fast = (a == 0.5f);
        float4 v = reinterpret_cast<const float4*>(x)[i];
        size_t e = i << 2;
        size_t row = e >> 11;                              // / IN_F
        size_t col = e & (IN_F - 1);
        float s[4] = {v.x, v.y, v.z, v.w};
        union { __nv_bfloat16 h[4]; uint2 u; } H, L;
#pragma unroll
        for (int k = 0; k < 4; k++) {
            float t  = s[k];
            float at = fabsf(t);
            float p  = fast ? sqrtf(at) : powf(at, a);
            float sc = copysignf(p, t);
            H.h[k] = __float2bfloat16(sc);
            L.h[k] = __float2bfloat16(sc - __bfloat162float(H.h[k]));
        }
        __nv_bfloat16* base = g_A + row * KK2 + col;
        *reinterpret_cast<uint2*>(base)        = H.u;
        *reinterpret_cast<uint2*>(base + IN_F) = L.u;
    } else {
        __shared__ float c[16];
        if (threadIdx.x < 16) c[threadIdx.x] = cent[threadIdx.x];
        __syncthreads();
        size_t i = (size_t)(bid - XB) * 256 + threadIdx.x; // int4 index
        int4 q = reinterpret_cast<const int4*>(wq)[i];
        size_t e = i << 2;
        size_t row = e >> 11;
        size_t col = e & (IN_F - 1);
        float w[4] = {c[q.x & 15], c[q.y & 15], c[q.z & 15], c[q.w & 15]};
        union { __nv_bfloat16 h[4]; uint2 u; } H, L;
#pragma unroll
        for (int k = 0; k < 4; k++) {
            H.h[k] = __float2bfloat16(w[k]);
            L.h[k] = __float2bfloat16(w[k] - __bfloat162float(H.h[k]));
        }
        __nv_bfloat16* base = g_W + row * KK2 + col;
        *reinterpret_cast<uint2*>(base)        = H.u;
        *reinterpret_cast<uint2*>(base + IN_F) = L.u;
    }
}

// ===================== GEMM kernel (mma.sync, 4-stage cp.async, 512 thr) =====================
static constexpr int BM = 128;
static constexpr int BN = 256;
static constexpr int KC = 64;                     // K elems per stage (128B rows)
static constexpr int STAGES = 4;
static constexpr int A_BYTES = BM * KC * 2;       // 16 KiB
static constexpr int B_BYTES = BN * KC * 2;       // 32 KiB
static constexpr int STG = A_BYTES + B_BYTES;     // 48 KiB
static constexpr int SMEM_TOTAL = STAGES * STG + 1024;
static constexpr int NKC = 3 * IN_F / KC;         // 96 K-chunks (3 split terms)
static constexpr int NTHR = 512;                  // 16 warps: 4(m) x 4(n), 32x64 warp tile

__global__ void __launch_bounds__(NTHR, 1)
gemm_kernel(float* __restrict__ out, const float* __restrict__ alpha) {
    extern __shared__ char smem_raw[];
    uint32_t sb = (smem_u32(smem_raw) + 1023u) & ~1023u;

    const int tid = threadIdx.x;
    const int wid = tid >> 5, lane = tid & 31;
    const int warp_m = wid & 3, warp_n = wid >> 2;        // 4 x 4 warps, 32x64 warp tile
    const int mb = blockIdx.x >> 3, nb = blockIdx.x & 7;  // n-minor for L2 A reuse
    const int m0 = mb * BM, n0 = nb * BN;

    const __nv_bfloat16* gA = g_A + (size_t)m0 * KK2;
    const __nv_bfloat16* gW = g_W + (size_t)n0 * KK2;

    // ---- ldmatrix per-lane address components ----
    const int a_row  = warp_m * 32 + (lane & 15);
    const int a_ext  = (lane >> 4) * 16;                  // k-halves (bytes)
    const int b_row  = warp_n * 64 + (lane & 7) + ((lane >> 4) << 3);
    const int b_ext  = ((lane >> 3) & 1) * 16;

    float acc[2][8][4];
#pragma unroll
    for (int im = 0; im < 2; im++)
#pragma unroll
        for (int in = 0; in < 8; in++)
#pragma unroll
            for (int r = 0; r < 4; r++) acc[im][in][r] = 0.0f;

    // K-chunk -> (acol, bcol): term0 hi/hi, term1 lo/hi, term2 hi/lo
    auto cols_of = [](int kc, int& acol, int& bcol) {
        int term = kc >> 5, inner = kc & 31;
        acol = ((term == 1) ? IN_F : 0) + inner * KC;
        bcol = ((term == 2) ? IN_F : 0) + inner * KC;
    };

    auto load_stage = [&](int slot, int kc) {
        int acol, bcol;
        cols_of(kc, acol, bcol);
        uint32_t sA = sb + slot * STG;
        uint32_t sB = sA + A_BYTES;
#pragma unroll
        for (int i = 0; i < 2; i++) {                      // A: 1024 chunks / 512 thr
            int c = tid + i * NTHR;
            int row = c >> 3, col = c & 7;
            cp16(sA + SWZ(row * 128 + col * 16), gA + (size_t)row * KK2 + acol + col * 8);
        }
#pragma unroll
        for (int i = 0; i < 4; i++) {                      // B: 2048 chunks / 512 thr
            int c = tid + i * NTHR;
            int row = c >> 3, col = c & 7;
            cp16(sB + SWZ(row * 128 + col * 16), gW + (size_t)row * KK2 + bcol + col * 8);
        }
    };

    // ---- prologue: stages 0..STAGES-2 ----
#pragma unroll
    for (int s = 0; s < STAGES - 1; s++) { load_stage(s, s); CP_COMMIT(); }

    // ---- main loop ----
    for (int kc = 0; kc < NKC; kc++) {
        CP_WAIT2();            // group kc complete (in-order groups)
        __syncthreads();       // data visible; all warps done reading slot being overwritten

        int nkc = kc + STAGES - 1;
        if (nkc < NKC) load_stage(nkc & (STAGES - 1), nkc);
        CP_COMMIT();           // one group per iter (may be empty)

        uint32_t sA = sb + (kc & (STAGES - 1)) * STG;
        uint32_t sB = sA + A_BYTES;

#pragma unroll
        for (int ks = 0; ks < 4; ks++) {
            uint32_t af[2][4], bf[4][4];
#pragma unroll
            for (int im = 0; im < 2; im++)
                ldsm_x4(af[im], sA + SWZ((a_row + im * 16) * 128 + ks * 32 + a_ext));
#pragma unroll
            for (int jn = 0; jn < 4; jn++)
                ldsm_x4(bf[jn], sB + SWZ((b_row + jn * 16) * 128 + ks * 32 + b_ext));
#pragma unroll
            for (int im = 0; im < 2; im++)
#pragma unroll
                for (int jn = 0; jn < 4; jn++) {
                    mma16816(acc[im][2 * jn + 0], af[im], bf[jn][0], bf[jn][1]);
                    mma16816(acc[im][2 * jn + 1], af[im], bf[jn][2], bf[jn][3]);
                }
        }
    }

    // ---- epilogue: y = sign(d) * |d|^(1/a) ----
    float a = alpha[0];
    bool fast = (a == 0.5f);
    float inv = 1.0f / a;
    const int er = m0 + warp_m * 32 + (lane >> 2);
    const int ec = n0 + warp_n * 64 + (lane & 3) * 2;
#pragma unroll
    for (int im = 0; im < 2; im++) {
#pragma unroll
        for (int in = 0; in < 8; in++) {
            float d0 = acc[im][in][0], d1 = acc[im][in][1];
            float d2 = acc[im][in][2], d3 = acc[im][in][3];
            float2 v01, v23;
            if (fast) {
                v01.x = d0 * fabsf(d0); v01.y = d1 * fabsf(d1);
                v23.x = d2 * fabsf(d2); v23.y = d3 * fabsf(d3);
            } else {
                v01.x = copysignf(powf(fabsf(d0), inv), d0);
                v01.y = copysignf(powf(fabsf(d1), inv), d1);
                v23.x = copysignf(powf(fabsf(d2), inv), d2);
                v23.y = copysignf(powf(fabsf(d3), inv), d3);
            }
            int row = er + im * 16;
            int col = ec + in * 8;
            *reinterpret_cast<float2*>(out + (size_t)row * OUT_F + col) = v01;
            *reinterpret_cast<float2*>(out + (size_t)(row + 8) * OUT_F + col) = v23;
        }
    }
}

// ===================== launch =====================
extern "C" void kernel_launch(void* const* d_in, const int* in_sizes, int n_in,
                              void* d_out, int out_size) {
    const float* x = nullptr;
    const float* cent = nullptr;
    const float* alpha = nullptr;
    const int*   wq = nullptr;
    for (int i = 0; i < n_in; i++) {
        long s = in_sizes[i];
        if      (s == (long)BATCH * IN_F) x     = (const float*)d_in[i];
        else if (s == 16)                 cent  = (const float*)d_in[i];
        else if (s == 1)                  alpha = (const float*)d_in[i];
        else if (s == (long)OUT_F * IN_F) wq    = (const int*)d_in[i];
    }

    cudaFuncSetAttribute(gemm_kernel, cudaFuncAttributeMaxDynamicSharedMemorySize, SMEM_TOTAL);

    convert_kernel<<<XB + WB, 256>>>(x, wq, cent, alpha);
    gemm_kernel<<<(BATCH / BM) * (OUT_F / BN), NTHR, SMEM_TOTAL>>>((float*)d_out, alpha);
}

// round 4
// speedup vs baseline: 1.0807x; 1.0600x over previous
#include <cuda_runtime.h>
#include <cuda_bf16.h>
#include <cstdint>
#include <cstddef>

// ===================== problem dims =====================
static constexpr int BATCH = 16384;
static constexpr int IN_F  = 2048;
static constexpr int OUT_F = 2048;
static constexpr int KK2   = 2 * IN_F;   // scratch K layout per row: [hi | lo]

// Effective GEMM: C = A_hi*W_hi + A_lo*W_hi + A_hi*W_lo  (bf16 inputs, fp32 accum)

// ===================== device scratch (no allocations allowed) =====================
__device__ __nv_bfloat16 g_A[(size_t)BATCH * KK2];  // 128 MiB
__device__ __nv_bfloat16 g_W[(size_t)OUT_F * KK2];  //  16 MiB

// ===================== helpers =====================
__device__ __forceinline__ uint32_t smem_u32(const void* p) {
    uint32_t a;
    asm("{ .reg .u64 t; cvta.to.shared.u64 t, %1; cvt.u32.u64 %0, t; }" : "=r"(a) : "l"(p));
    return a;
}
__device__ __forceinline__ void cp16(uint32_t smem_dst, const void* gmem_src) {
    asm volatile("cp.async.cg.shared.global [%0], [%1], 16;" :: "r"(smem_dst), "l"(gmem_src));
}
#define CP_COMMIT() asm volatile("cp.async.commit_group;" ::: "memory")
#define CP_WAIT1()  asm volatile("cp.async.wait_group 1;" ::: "memory")

__device__ __forceinline__ void ldsm_x4(uint32_t (&r)[4], uint32_t addr) {
    asm volatile("ldmatrix.sync.aligned.m8n8.x4.shared.b16 {%0,%1,%2,%3}, [%4];"
                 : "=r"(r[0]), "=r"(r[1]), "=r"(r[2]), "=r"(r[3]) : "r"(addr));
}
__device__ __forceinline__ void mma16816(float (&d)[4], const uint32_t (&a)[4],
                                         uint32_t b0, uint32_t b1) {
    asm volatile(
        "mma.sync.aligned.m16n8k16.row.col.f32.bf16.bf16.f32 "
        "{%0,%1,%2,%3}, {%4,%5,%6,%7}, {%8,%9}, {%0,%1,%2,%3};"
        : "+f"(d[0]), "+f"(d[1]), "+f"(d[2]), "+f"(d[3])
        : "r"(a[0]), "r"(a[1]), "r"(a[2]), "r"(a[3]), "r"(b0), "r"(b1));
}

// SW128 swizzle (Swizzle<3,4,3>) — tile bases must be 1024B aligned
#define SWZ(o) ((o) ^ (((o) >> 3) & 0x70))

// ===================== merged conversion kernel =====================
static constexpr int XB = (BATCH * IN_F / 4) / 256;   // 32768 blocks
static constexpr int WB = (OUT_F * IN_F / 4) / 256;   //  4096 blocks

__global__ void convert_kernel(const float* __restrict__ x,
                               const int* __restrict__ wq,
                               const float* __restrict__ cent,
                               const float* __restrict__ alpha) {
    int bid = blockIdx.x;
    if (bid < XB) {
        size_t i = (size_t)bid * 256 + threadIdx.x;        // float4 index
        float a = alpha[0];
        bool fast = (a == 0.5f);
        float4 v = reinterpret_cast<const float4*>(x)[i];
        size_t e = i << 2;
        size_t row = e >> 11;                              // / IN_F
        size_t col = e & (IN_F - 1);
        float s[4] = {v.x, v.y, v.z, v.w};
        union { __nv_bfloat16 h[4]; uint2 u; } H, L;
#pragma unroll
        for (int k = 0; k < 4; k++) {
            float t  = s[k];
            float at = fabsf(t);
            float p  = fast ? sqrtf(at) : powf(at, a);
            float sc = copysignf(p, t);
            H.h[k] = __float2bfloat16(sc);
            L.h[k] = __float2bfloat16(sc - __bfloat162float(H.h[k]));
        }
        __nv_bfloat16* base = g_A + row * KK2 + col;
        *reinterpret_cast<uint2*>(base)        = H.u;
        *reinterpret_cast<uint2*>(base + IN_F) = L.u;
    } else {
        __shared__ float c[16];
        if (threadIdx.x < 16) c[threadIdx.x] = cent[threadIdx.x];
        __syncthreads();
        size_t i = (size_t)(bid - XB) * 256 + threadIdx.x; // int4 index
        int4 q = reinterpret_cast<const int4*>(wq)[i];
        size_t e = i << 2;
        size_t row = e >> 11;
        size_t col = e & (IN_F - 1);
        float w[4] = {c[q.x & 15], c[q.y & 15], c[q.z & 15], c[q.w & 15]};
        union { __nv_bfloat16 h[4]; uint2 u; } H, L;
#pragma unroll
        for (int k = 0; k < 4; k++) {
            H.h[k] = __float2bfloat16(w[k]);
            L.h[k] = __float2bfloat16(w[k] - __bfloat162float(H.h[k]));
        }
        __nv_bfloat16* base = g_W + row * KK2 + col;
        *reinterpret_cast<uint2*>(base)        = H.u;
        *reinterpret_cast<uint2*>(base + IN_F) = L.u;
    }
}

// ===================== GEMM kernel (mma.sync, 3-stage cp.async, 2 CTA/SM) =====================
static constexpr int BM = 128;
static constexpr int BN = 128;
static constexpr int KC = 64;                     // K elems per stage (128B rows)
static constexpr int STAGES = 3;
static constexpr int A_BYTES = BM * KC * 2;       // 16 KiB
static constexpr int B_BYTES = BN * KC * 2;       // 16 KiB
static constexpr int STG = A_BYTES + B_BYTES;     // 32 KiB
static constexpr int SMEM_TOTAL = STAGES * STG;   // 96 KiB (dynamic smem is 1024-aligned)
static constexpr int NKC = 3 * IN_F / KC;         // 96 K-chunks (3 split terms)
static constexpr int NTHR = 256;                  // 8 warps: 4(m) x 2(n), 32x64 warp tile
static constexpr int NB_PER_M = OUT_F / BN;       // 16 n-blocks

__global__ void __launch_bounds__(NTHR, 2)
gemm_kernel(float* __restrict__ out, const float* __restrict__ alpha) {
    extern __shared__ char smem_raw[];
    uint32_t sb = smem_u32(smem_raw);

    const int tid = threadIdx.x;
    const int wid = tid >> 5, lane = tid & 31;
    const int warp_m = wid & 3, warp_n = wid >> 2;          // 4 x 2 warps
    const int mb = blockIdx.x >> 4, nb = blockIdx.x & 15;   // n-minor: L2 A reuse
    const int m0 = mb * BM, n0 = nb * BN;

    const __nv_bfloat16* gA = g_A + (size_t)m0 * KK2;
    const __nv_bfloat16* gW = g_W + (size_t)n0 * KK2;

    // ---- ldmatrix per-lane address components ----
    const int a_row  = warp_m * 32 + (lane & 15);
    const int a_ext  = (lane >> 4) * 16;                    // k-half (bytes)
    const int b_row  = warp_n * 64 + (lane & 7) + ((lane >> 4) << 3);
    const int b_ext  = ((lane >> 3) & 1) * 16;

    float acc[2][8][4];
#pragma unroll
    for (int im = 0; im < 2; im++)
#pragma unroll
        for (int in = 0; in < 8; in++)
#pragma unroll
            for (int r = 0; r < 4; r++) acc[im][in][r] = 0.0f;

    // K-chunk -> (acol, bcol): term0 hi/hi, term1 lo/hi, term2 hi/lo
    auto cols_of = [](int kc, int& acol, int& bcol) {
        int term = kc >> 5, inner = kc & 31;
        acol = ((term == 1) ? IN_F : 0) + inner * KC;
        bcol = ((term == 2) ? IN_F : 0) + inner * KC;
    };

    auto load_stage = [&](int slot, int kc) {
        int acol, bcol;
        cols_of(kc, acol, bcol);
        uint32_t sA = sb + slot * STG;
        uint32_t sB = sA + A_BYTES;
#pragma unroll
        for (int i = 0; i < 4; i++) {                        // A: 1024 chunks / 256 thr
            int c = tid + i * NTHR;
            int row = c >> 3, col = c & 7;
            cp16(sA + SWZ(row * 128 + col * 16), gA + (size_t)row * KK2 + acol + col * 8);
        }
#pragma unroll
        for (int i = 0; i < 4; i++) {                        // B: 1024 chunks / 256 thr
            int c = tid + i * NTHR;
            int row = c >> 3, col = c & 7;
            cp16(sB + SWZ(row * 128 + col * 16), gW + (size_t)row * KK2 + bcol + col * 8);
        }
    };

    // ---- prologue: 2 stages in flight ----
    load_stage(0, 0); CP_COMMIT();
    load_stage(1, 1); CP_COMMIT();

    // ---- main loop ----
    int slot = 0, nslot = 2;
    for (int kc = 0; kc < NKC; kc++) {
        CP_WAIT1();            // group kc complete (<=1 group still in flight)
        __syncthreads();       // data visible; all warps done with slot being overwritten

        int nkc = kc + STAGES - 1;
        if (nkc < NKC) load_stage(nslot, nkc);
        CP_COMMIT();           // one group per iter (may be empty)

        uint32_t sA = sb + slot * STG;
        uint32_t sB = sA + A_BYTES;

#pragma unroll
        for (int ks = 0; ks < 4; ks++) {
            uint32_t af[2][4], bf[2][4];
#pragma unroll
            for (int im = 0; im < 2; im++)
                ldsm_x4(af[im], sA + SWZ((a_row + im * 16) * 128 + ks * 32 + a_ext));
#pragma unroll
            for (int jn = 0; jn < 2; jn++)
                ldsm_x4(bf[jn], sB + SWZ((b_row + jn * 16) * 128 + ks * 32 + b_ext));
#pragma unroll
            for (int im = 0; im < 2; im++)
#pragma unroll
                for (int jn = 0; jn < 2; jn++) {
                    mma16816(acc[im][2 * jn + 0], af[im], bf[jn][0], bf[jn][1]);
                    mma16816(acc[im][2 * jn + 1], af[im], bf[jn][2], bf[jn][3]);
                }
        }
        // wait, 32x64 warp tile needs 4 n sub-tiles of 16 — bf covers 2x16=32 cols; do other half
#pragma unroll
        for (int ks = 0; ks < 4; ks++) {
            uint32_t af[2][4], bf[2][4];
#pragma unroll
            for (int im = 0; im < 2; im++)
                ldsm_x4(af[im], sA + SWZ((a_row + im * 16) * 128 + ks * 32 + a_ext));
#pragma unroll
            for (int jn = 0; jn < 2; jn++)
                ldsm_x4(bf[jn], sB + SWZ((b_row + 32 + jn * 16) * 128 + ks * 32 + b_ext));
#pragma unroll
            for (int im = 0; im < 2; im++)
#pragma unroll
                for (int jn = 0; jn < 2; jn++) {
                    mma16816(acc[im][4 + 2 * jn + 0], af[im], bf[jn][0], bf[jn][1]);
                    mma16816(acc[im][4 + 2 * jn + 1], af[im], bf[jn][2], bf[jn][3]);
                }
        }

        slot = (slot == STAGES - 1) ? 0 : slot + 1;
        nslot = (nslot == STAGES - 1) ? 0 : nslot + 1;
    }

    // ---- epilogue: y = sign(d) * |d|^(1/a) ----
    float a = alpha[0];
    bool fast = (a == 0.5f);
    float inv = 1.0f / a;
    const int er = m0 + warp_m * 32 + (lane >> 2);
    const int ec = n0 + warp_n * 64 + (lane & 3) * 2;
#pragma unroll
    for (int im = 0; im < 2; im++) {
#pragma unroll
        for (int in = 0; in < 8; in++) {
            float d0 = acc[im][in][0], d1 = acc[im][in][1];
            float d2 = acc[im][in][2], d3 = acc[im][in][3];
            float2 v01, v23;
            if (fast) {
                v01.x = d0 * fabsf(d0); v01.y = d1 * fabsf(d1);
                v23.x = d2 * fabsf(d2); v23.y = d3 * fabsf(d3);
            } else {
                v01.x = copysignf(powf(fabsf(d0), inv), d0);
                v01.y = copysignf(powf(fabsf(d1), inv), d1);
                v23.x = copysignf(powf(fabsf(d2), inv), d2);
                v23.y = copysignf(powf(fabsf(d3), inv), d3);
            }
            // acc[im][in]: in = sub-half*4 + 2*jn + (0|1); cols: half*32 + jn*16 + b*8
            int half = in >> 2, rem = in & 3;
            int jn = rem >> 1, b = rem & 1;
            int row = er + im * 16;
            int col = ec + half * 32 + jn * 16 + b * 8;
            *reinterpret_cast<float2*>(out + (size_t)row * OUT_F + col) = v01;
            *reinterpret_cast<float2*>(out + (size_t)(row + 8) * OUT_F + col) = v23;
        }
    }
}

// ===================== launch =====================
extern "C" void kernel_launch(void* const* d_in, const int* in_sizes, int n_in,
                              void* d_out, int out_size) {
    const float* x = nullptr;
    const float* cent = nullptr;
    const float* alpha = nullptr;
    const int*   wq = nullptr;
    for (int i = 0; i < n_in; i++) {
        long s = in_sizes[i];
        if      (s == (long)BATCH * IN_F) x     = (const float*)d_in[i];
        else if (s == 16)                 cent  = (const float*)d_in[i];
        else if (s == 1)                  alpha = (const float*)d_in[i];
        else if (s == (long)OUT_F * IN_F) wq    = (const int*)d_in[i];
    }

    cudaFuncSetAttribute(gemm_kernel, cudaFuncAttributeMaxDynamicSharedMemorySize, SMEM_TOTAL);

    convert_kernel<<<XB + WB, 256>>>(x, wq, cent, alpha);
    gemm_kernel<<<(BATCH / BM) * NB_PER_M, NTHR, SMEM_TOTAL>>>((float*)d_out, alpha);
}